// round 11
// baseline (speedup 1.0000x reference)
#include <cuda_runtime.h>
#include <stdint.h>

// Shapes (fixed by the problem)
#define BATCH 32
#define SEQ   4096
#define VOCAB 10
#define FEAT  1024
#define DIM   64

#define CHUNK   256
#define THREADS 256
#define NCTAS   (BATCH * (SEQ / CHUNK))    // 512
#define NPAIRS  (DIM * VOCAB)              // 640

// Projected table P[d][v] + sync state
__device__ float    g_P[NPAIRS];
__device__ unsigned g_cnt;                 // pairs published
__device__ unsigned g_fin;                 // CTAs finished (replay reset)

__device__ __forceinline__ unsigned ld_acquire(const unsigned* p) {
    unsigned v;
    asm volatile("ld.acquire.gpu.global.u32 %0, [%1];" : "=r"(v) : "l"(p));
    return v;
}

// One warp computes one (d,v) dot product and publishes it.
__device__ __forceinline__ void produce_pair(int pid, int lane,
                                             const float* __restrict__ fp,
                                             const float* __restrict__ W,
                                             const float* __restrict__ bias) {
    const int d = pid / VOCAB;
    const int v = pid - d * VOCAB;

    const float4* fr = reinterpret_cast<const float4*>(fp + v * FEAT);
    const float4* wr = reinterpret_cast<const float4*>(W  + d * FEAT);

    float s = 0.f;
#pragma unroll
    for (int f = lane; f < FEAT / 4; f += 32) {   // 8 iters, 16 LDG.128
        float4 a = fr[f];
        float4 c = wr[f];
        s += a.x * c.x + a.y * c.y + a.z * c.z + a.w * c.w;
    }
#pragma unroll
    for (int o = 16; o > 0; o >>= 1)
        s += __shfl_down_sync(0xffffffffu, s, o);

    if (lane == 0) {
        g_P[pid] = s + bias[d];
        __threadfence();                   // publish before counting
        atomicAdd(&g_cnt, 1u);
    }
}

// ---------------------------------------------------------------------------
// Single fused kernel, 512 CTAs (all wave-1 resident; capacity >= 592).
// Each CTA: prefetch its indices, compute its 1-2 P pairs (warps 0/1),
// wait for all 640 pairs, then run the proven gather loop.
//   pair ids: CTA c owns pid=c, and pid=512+c when c<128  -> 640 total.
// ---------------------------------------------------------------------------
__global__ void __launch_bounds__(THREADS)
fused_kernel(const int* __restrict__ idx,
             const float* __restrict__ fp,
             const float* __restrict__ W,
             const float* __restrict__ bias,
             float* __restrict__ out) {
    __shared__ float sP[NPAIRS];

    const int tid = threadIdx.x;
    const int bid = blockIdx.x;
    const int wid = tid >> 5;
    const int lane = tid & 31;

    const int b   = bid >> 4;              // 16 chunks per batch row
    const int l0  = (bid & 15) * CHUNK;
    const int lq  = tid & 63;              // float4 slot (fixed per thread)
    const int db  = tid >> 6;              // base d-row (0..3)

    // P-independent prefetch: this thread's 4 vocab indices (coalesced 16B)
    int4 iv = *reinterpret_cast<const int4*>(idx + b * SEQ + l0 + lq * 4);

    // Produce this CTA's share of P (warp 0 always, warp 1 for bid<128)
    if (wid == 0)                    produce_pair(bid,       lane, fp, W, bias);
    else if (wid == 1 && bid < 128)  produce_pair(512 + bid, lane, fp, W, bias);

    // Wait until all 640 pairs are published
    if (tid == 0) {
        while (ld_acquire(&g_cnt) < NPAIRS) { }
    }
    __syncthreads();

    // Table into shared: [d][v]
    for (int i = tid; i < NPAIRS; i += THREADS)
        sP[i] = g_P[i];
    __syncthreads();

    // Gather: 64 conflict-free LDS + 16 coalesced STG.128 per thread
    float* ob = out + (b * DIM) * SEQ + l0 + lq * 4;
#pragma unroll
    for (int k = 0; k < 16; k++) {
        const int d = db + 4 * k;
        const float* p = &sP[d * VOCAB];
        float4 r;
        r.x = p[iv.x];
        r.y = p[iv.y];
        r.z = p[iv.z];
        r.w = p[iv.w];
        *reinterpret_cast<float4*>(ob + d * SEQ) = r;
    }

    // Replay reset: last CTA to finish zeroes the counters
    __syncthreads();
    if (tid == 0) {
        unsigned done = atomicAdd(&g_fin, 1u);
        if (done == NCTAS - 1) {
            atomicExch(&g_cnt, 0u);
            atomicExch(&g_fin, 0u);
        }
    }
}

// ---------------------------------------------------------------------------
// Inputs per metadata order: indices (int32), fp_table (f32), W (f32), b (f32)
// ---------------------------------------------------------------------------
extern "C" void kernel_launch(void* const* d_in, const int* in_sizes, int n_in,
                              void* d_out, int out_size) {
    const int*   idx  = (const int*)d_in[0];
    const float* fp   = (const float*)d_in[1];
    const float* W    = (const float*)d_in[2];
    const float* bias = (const float*)d_in[3];
    float*       out  = (float*)d_out;

    fused_kernel<<<NCTAS, THREADS>>>(idx, fp, W, bias, out);
}

// round 12
// speedup vs baseline: 1.0512x; 1.0512x over previous
#include <cuda_runtime.h>
#include <stdint.h>

// Shapes (fixed by the problem)
#define BATCH 32
#define SEQ   4096
#define VOCAB 10
#define FEAT  1024
#define DIM   64

#define CHUNK   256
#define THREADS 256
#define HALF    32                     // d-rows via TMA; the rest via STG

// Precomputed projected table: P[d][v] = b[d] + sum_f fp[v][f] * W[d][f]
__device__ float g_P[DIM * VOCAB];

// ---------------------------------------------------------------------------
// Kernel 1: tiny 10x64x1024 GEMM. One warp per (d, v) pair -> 640 warps.
// ---------------------------------------------------------------------------
__global__ void compute_P_kernel(const float* __restrict__ fp,
                                 const float* __restrict__ W,
                                 const float* __restrict__ bias) {
    int w    = (blockIdx.x * blockDim.x + threadIdx.x) >> 5;
    int lane = threadIdx.x & 31;
    int d = w / VOCAB;
    int v = w - d * VOCAB;

    const float4* fr = reinterpret_cast<const float4*>(fp + v * FEAT);
    const float4* wr = reinterpret_cast<const float4*>(W  + d * FEAT);

    float s = 0.f;
#pragma unroll
    for (int f = lane; f < FEAT / 4; f += 32) {
        float4 a = fr[f];
        float4 c = wr[f];
        s += a.x * c.x + a.y * c.y + a.z * c.z + a.w * c.w;
    }

#pragma unroll
    for (int o = 16; o > 0; o >>= 1)
        s += __shfl_down_sync(0xffffffffu, s, o);

    if (lane == 0)
        g_P[d * VOCAB + v] = s + bias[d];

    __threadfence();
    cudaTriggerProgrammaticLaunchCompletion();
}

// ---------------------------------------------------------------------------
// Kernel 2: HYBRID drain. d-rows 0..31 -> direct STG.128 (SM store path),
// d-rows 32..63 -> smem tile + cp.async.bulk 1KB row copies (TMA path).
// Probes whether the two write paths into L2 are additive.
// ---------------------------------------------------------------------------
__global__ void __launch_bounds__(THREADS)
gather_kernel(const int* __restrict__ idx, float* __restrict__ out) {
    __shared__ float sP[DIM * VOCAB];
    __shared__ __align__(128) float tile[HALF * CHUNK];   // 32 KB

    const int b   = blockIdx.y;
    const int l0  = blockIdx.x * CHUNK;
    const int tid = threadIdx.x;
    const int lq  = tid & 63;            // float4 slot within chunk (fixed)
    const int db  = tid >> 6;            // base d-row (0..3)

    // P-independent prelude: this thread's 4 vocab indices (coalesced 16B)
    int4 iv = *reinterpret_cast<const int4*>(idx + b * SEQ + l0 + lq * 4);

    cudaGridDependencySynchronize();     // wait for compute_P_kernel

    for (int i = tid; i < DIM * VOCAB; i += THREADS)
        sP[i] = g_P[i];
    __syncthreads();

    float* ob = out + (b * DIM) * SEQ + l0 + lq * 4;

    // --- TMA half first: fill the smem tile for d-rows 32..63 ---
#pragma unroll
    for (int k = 0; k < 8; k++) {
        const int d = HALF + db + 4 * k;          // 32..63
        const float* p = &sP[d * VOCAB];
        float4 r;
        r.x = p[iv.x];
        r.y = p[iv.y];
        r.z = p[iv.z];
        r.w = p[iv.w];
        *reinterpret_cast<float4*>(&tile[(d - HALF) * CHUNK + lq * 4]) = r;
    }
    __syncthreads();
    asm volatile("fence.proxy.async.shared::cta;" ::: "memory");

    // Kick off 32 x 1KB bulk stores (TMA engine works while we keep STG-ing)
    if (tid < HALF) {
        uint32_t src;
        asm("{ .reg .u64 t; cvta.to.shared.u64 t, %1; cvt.u32.u64 %0, t; }"
            : "=r"(src) : "l"(tile + tid * CHUNK));
        float* dst = out + (b * DIM + HALF + tid) * SEQ + l0;
        asm volatile(
            "cp.async.bulk.global.shared::cta.bulk_group [%0], [%1], %2;"
            :: "l"(dst), "r"(src), "n"(CHUNK * 4) : "memory");
        asm volatile("cp.async.bulk.commit_group;" ::: "memory");
    }

    // --- STG half concurrently: d-rows 0..31 via per-thread stores ---
#pragma unroll
    for (int k = 0; k < 8; k++) {
        const int d = db + 4 * k;                 // 0..31
        const float* p = &sP[d * VOCAB];
        float4 r;
        r.x = p[iv.x];
        r.y = p[iv.y];
        r.z = p[iv.z];
        r.w = p[iv.w];
        *reinterpret_cast<float4*>(ob + d * SEQ) = r;
    }

    // Drain outstanding bulk stores before the CTA may exit
    if (tid < HALF)
        asm volatile("cp.async.bulk.wait_group 0;" ::: "memory");
}

// ---------------------------------------------------------------------------
// Inputs per metadata order: indices (int32), fp_table (f32), W (f32), b (f32)
// ---------------------------------------------------------------------------
extern "C" void kernel_launch(void* const* d_in, const int* in_sizes, int n_in,
                              void* d_out, int out_size) {
    const int*   idx  = (const int*)d_in[0];
    const float* fp   = (const float*)d_in[1];
    const float* W    = (const float*)d_in[2];
    const float* bias = (const float*)d_in[3];
    float*       out  = (float*)d_out;

    compute_P_kernel<<<80, 256>>>(fp, W, bias);

    cudaLaunchConfig_t cfg = {};
    cfg.gridDim          = dim3(SEQ / CHUNK, BATCH);   // (16, 32) = 512 CTAs
    cfg.blockDim         = dim3(THREADS, 1, 1);
    cfg.dynamicSmemBytes = 0;
    cfg.stream           = 0;

    cudaLaunchAttribute attr[1];
    attr[0].id = cudaLaunchAttributeProgrammaticStreamSerialization;
    attr[0].val.programmaticStreamSerializationAllowed = 1;
    cfg.attrs    = attr;
    cfg.numAttrs = 1;

    cudaLaunchKernelEx(&cfg, gather_kernel, idx, out);
}